// round 1
// baseline (speedup 1.0000x reference)
#include <cuda_runtime.h>

// Idx2PixelLayer: bilinear gather of N=1e6 points from a 2048x2048x8 fp32 image.
// c = ((coord - 1) mod (dim - 4)) + 1   (non-negative mod, JAX semantics)
// out = w00*g(0,0) + w10*g(1,0) + w01*g(0,1) + w11*g(1,1)
//   with w00=d0*d1, w10=(1-d0)*d1, w01=d0*(1-d1), w11=(1-d0)*(1-d1)
// (g(di,dj) = visible[i0+di][i1+dj]; reference's off-mask is always false since
//  c <= 2045 < 2048.)

static constexpr int H = 2048;
static constexpr int W = 2048;
static constexpr int C = 8;
static constexpr int NPTS = 1000000;

__global__ __launch_bounds__(256)
void idx2pixel_kernel(const float* __restrict__ coords,
                      const float* __restrict__ visible,
                      float* __restrict__ out,
                      int n)
{
    int t = blockIdx.x * blockDim.x + threadIdx.x;
    if (t >= n) return;

    // coords[t] = (x0, x1)
    float2 xy = __ldg(reinterpret_cast<const float2*>(coords) + t);

    const float m0 = (float)(H - 4);   // 2044
    const float m1 = (float)(W - 4);

    float c0 = fmodf(xy.x - 1.0f, m0); if (c0 < 0.0f) c0 += m0; c0 += 1.0f;
    float c1 = fmodf(xy.y - 1.0f, m1); if (c1 < 0.0f) c1 += m1; c1 += 1.0f;

    float f0 = floorf(c0);
    float f1 = floorf(c1);
    float d0 = c0 - f0;
    float d1 = c1 - f1;
    int   i0 = (int)f0;
    int   i1 = (int)f1;

    // base offset in floats: pixel (i0, i1), channel stride 1, col stride C, row stride W*C
    int base = (i0 * W + i1) * C;
    const float4* p00 = reinterpret_cast<const float4*>(visible + base);            // g(0,0)
    const float4* p01 = reinterpret_cast<const float4*>(visible + base + C);        // g(0,1)
    const float4* p10 = reinterpret_cast<const float4*>(visible + base + W * C);    // g(1,0)
    const float4* p11 = reinterpret_cast<const float4*>(visible + base + W * C + C);// g(1,1)

    // Front-batch all 8 gathered loads for max MLP.
    float4 a00 = __ldg(p00 + 0), b00 = __ldg(p00 + 1);
    float4 a01 = __ldg(p01 + 0), b01 = __ldg(p01 + 1);
    float4 a10 = __ldg(p10 + 0), b10 = __ldg(p10 + 1);
    float4 a11 = __ldg(p11 + 0), b11 = __ldg(p11 + 1);

    float w00 = d0 * d1;
    float w10 = (1.0f - d0) * d1;
    float w01 = d0 * (1.0f - d1);
    float w11 = (1.0f - d0) * (1.0f - d1);

    float4 oa, ob;
    oa.x = w00 * a00.x + w10 * a10.x + w01 * a01.x + w11 * a11.x;
    oa.y = w00 * a00.y + w10 * a10.y + w01 * a01.y + w11 * a11.y;
    oa.z = w00 * a00.z + w10 * a10.z + w01 * a01.z + w11 * a11.z;
    oa.w = w00 * a00.w + w10 * a10.w + w01 * a01.w + w11 * a11.w;
    ob.x = w00 * b00.x + w10 * b10.x + w01 * b01.x + w11 * b11.x;
    ob.y = w00 * b00.y + w10 * b10.y + w01 * b01.y + w11 * b11.y;
    ob.z = w00 * b00.z + w10 * b10.z + w01 * b01.z + w11 * b11.z;
    ob.w = w00 * b00.w + w10 * b10.w + w01 * b01.w + w11 * b11.w;

    float4* o = reinterpret_cast<float4*>(out + t * C);
    o[0] = oa;
    o[1] = ob;
}

extern "C" void kernel_launch(void* const* d_in, const int* in_sizes, int n_in,
                              void* d_out, int out_size)
{
    const float* coords  = (const float*)d_in[0];  // [N, 2] fp32
    const float* visible = (const float*)d_in[1];  // [H, W, C] fp32
    float* out = (float*)d_out;                    // [N, C] fp32

    int n = in_sizes[0] / 2;   // number of points
    (void)n_in; (void)out_size; (void)NPTS;

    int threads = 256;
    int blocks = (n + threads - 1) / threads;
    idx2pixel_kernel<<<blocks, threads>>>(coords, visible, out, n);
}

// round 3
// speedup vs baseline: 1.2327x; 1.2327x over previous
#include <cuda_runtime.h>

// Idx2PixelLayer: bilinear gather of N=1e6 points from a 2048x2048x8 fp32 image.
// c = ((coord - 1) mod (dim - 4)) + 1   (non-negative mod, JAX semantics)
// out = w00*g(0,0) + w10*g(1,0) + w01*g(0,1) + w11*g(1,1)
//   w00=d0*d1, w10=(1-d0)*d1, w01=d0*(1-d1), w11=(1-d0)*(1-d1)
// Reference's off-mask is always false (c <= 2045 < 2048), so dropped.
//
// Layout: 2 threads per point. Thread half k (=tid&1) handles channels 4k..4k+3.
// Lane pairs access adjacent 16B halves of the same 32B pixel sector, so each
// gather instruction generates ONE L1tex wavefront per point (4 wf/pt total,
// vs 8 for 1-thread/pt). Output via __stcs / coords via __ldcs to keep the
// 128MB image resident in the ~126MB L2 across graph replays.

static constexpr int H = 2048;
static constexpr int W = 2048;
static constexpr int C = 8;

__global__ __launch_bounds__(256)
void idx2pixel_kernel(const float* __restrict__ coords,
                      const float* __restrict__ visible,
                      float* __restrict__ out,
                      int n)  // n = number of points
{
    int t = blockIdx.x * blockDim.x + threadIdx.x;
    int p = t >> 1;          // point index
    int k = t & 1;           // channel half: floats [4k, 4k+4)
    if (p >= n) return;

    // Both lanes of a pair read the same float2 (coalesced; streaming hint).
    float2 xy = __ldcs(reinterpret_cast<const float2*>(coords) + p);

    const float m0 = (float)(H - 4);   // 2044
    const float m1 = (float)(W - 4);

    float c0 = fmodf(xy.x - 1.0f, m0); if (c0 < 0.0f) c0 += m0; c0 += 1.0f;
    float c1 = fmodf(xy.y - 1.0f, m1); if (c1 < 0.0f) c1 += m1; c1 += 1.0f;

    float f0 = floorf(c0);
    float f1 = floorf(c1);
    float d0 = c0 - f0;
    float d1 = c1 - f1;
    int   i0 = (int)f0;
    int   i1 = (int)f1;

    // base in floats: pixel (i0,i1), + channel-half offset 4k
    int base = (i0 * W + i1) * C + 4 * k;

    const float4* p00 = reinterpret_cast<const float4*>(visible + base);             // g(0,0)
    const float4* p01 = reinterpret_cast<const float4*>(visible + base + C);         // g(0,1)
    const float4* p10 = reinterpret_cast<const float4*>(visible + base + W * C);     // g(1,0)
    const float4* p11 = reinterpret_cast<const float4*>(visible + base + W * C + C); // g(1,1)

    // Front-batch the 4 gathers for MLP.
    float4 a00 = __ldg(p00);
    float4 a01 = __ldg(p01);
    float4 a10 = __ldg(p10);
    float4 a11 = __ldg(p11);

    float w00 = d0 * d1;
    float w10 = (1.0f - d0) * d1;
    float w01 = d0 * (1.0f - d1);
    float w11 = (1.0f - d0) * (1.0f - d1);

    float4 o;
    o.x = w00 * a00.x + w10 * a10.x + w01 * a01.x + w11 * a11.x;
    o.y = w00 * a00.y + w10 * a10.y + w01 * a01.y + w11 * a11.y;
    o.z = w00 * a00.z + w10 * a10.z + w01 * a01.z + w11 * a11.z;
    o.w = w00 * a00.w + w10 * a10.w + w01 * a01.w + w11 * a11.w;

    // Consecutive lanes write consecutive float4s — fully coalesced.
    // Streaming store: don't let output thrash the image out of L2.
    __stcs(reinterpret_cast<float4*>(out + p * C + 4 * k), o);
}

extern "C" void kernel_launch(void* const* d_in, const int* in_sizes, int n_in,
                              void* d_out, int out_size)
{
    const float* coords  = (const float*)d_in[0];  // [N, 2] fp32
    const float* visible = (const float*)d_in[1];  // [H, W, C] fp32
    float* out = (float*)d_out;                    // [N, C] fp32

    int n = in_sizes[0] / 2;   // number of points
    (void)n_in; (void)out_size;

    int threads = 256;
    int total = 2 * n;         // 2 threads per point
    int blocks = (total + threads - 1) / threads;
    idx2pixel_kernel<<<blocks, threads>>>(coords, visible, out, n);
}